// round 6
// baseline (speedup 1.0000x reference)
#include <cuda_runtime.h>

#define C16  16
#define GH32 32
#define W512 512
#define HW   (512 * 512)

// Constant-bank weight layout (floats). ALL weights live here now: LDC uses
// the dedicated constant port, keeping the L1tex pipe for the x gather only.
#define OFF_W1 0        // [c][j]      16*32
#define OFF_W2 512      // [c][j]      16*32  (= g1w[:,16:] @ mw, folded)
#define OFF_G2 1024     // [gp][j][e]  8*32*2 (= g2w[2gp+e][j])
#define OFF_MW 1536     // [c][d]      16*16  (= mw[d][c])
#define OFF_B1 1792     // 32          (= g1b + g1w[:,16:] @ mb)
#define OFF_GB 1824     // 16          (g2b)
#define OFF_MB 1840     // 16          (mb)
#define NWC    1856

__constant__ __align__(16) float cwts[NWC];
__device__   __align__(16) float g_wbuf[NWC];

// Packed f32x2 FMA (Blackwell sm_103a) — 2 fp32 FMAs per instruction.
__device__ __forceinline__ float2 ffma2(float2 a, float2 b, float2 c) {
    float2 d;
    asm("fma.rn.f32x2 %0, %1, %2, %3;"
        : "=l"(reinterpret_cast<unsigned long long&>(d))
        : "l"(reinterpret_cast<unsigned long long&>(a)),
          "l"(reinterpret_cast<unsigned long long&>(b)),
          "l"(reinterpret_cast<unsigned long long&>(c)));
    return d;
}
__device__ __forceinline__ float2 dup2(float v) { return make_float2(v, v); }
__device__ __forceinline__ float4 ldc4(int idx) {
    return *reinterpret_cast<const float4*>(&cwts[idx]);
}
__device__ __forceinline__ float2 ldc2(int idx) {
    return *reinterpret_cast<const float2*>(&cwts[idx]);
}

// ---- prep: fold weights into constant-bank staging buffer ----
__global__ void prep_weights(const float* __restrict__ mw,  const float* __restrict__ mb,
                             const float* __restrict__ g1w, const float* __restrict__ g1b,
                             const float* __restrict__ g2w, const float* __restrict__ g2b)
{
    const int t = threadIdx.x;
    for (int i = t; i < C16 * GH32; i += 256) {
        int c = i >> 5, j = i & 31;
        g_wbuf[OFF_W1 + i] = g1w[j * (2 * C16) + c];
        float acc = 0.f;
        #pragma unroll
        for (int k = 0; k < C16; k++)
            acc += g1w[j * (2 * C16) + C16 + k] * mw[k * C16 + c];
        g_wbuf[OFF_W2 + i] = acc;
    }
    for (int i = t; i < 8 * GH32 * 2; i += 256) {
        int gp = i >> 6, r = i & 63, j = r >> 1, e = r & 1;
        g_wbuf[OFF_G2 + i] = g2w[(2 * gp + e) * GH32 + j];
    }
    if (t < 256) {
        int c = t >> 4, d = t & 15;
        g_wbuf[OFF_MW + t] = mw[d * C16 + c];
    }
    if (t < GH32) {
        float acc = g1b[t];
        #pragma unroll
        for (int k = 0; k < C16; k++)
            acc += g1w[t * (2 * C16) + C16 + k] * mb[k];
        g_wbuf[OFF_B1 + t] = acc;
    }
    if (t >= 32 && t < 32 + C16) g_wbuf[OFF_MB + t - 32] = mb[t - 32];
    if (t >= 64 && t < 64 + C16) g_wbuf[OFF_GB + t - 64] = g2b[t - 64];
}

// Identity: softmax over 8 identical affinities = 1/8 each, so
//   s      = mean of 8 rolls of x
//   agg    = mw @ s + mb
//   hidden = relu(W1 @ x + W2 @ s + b1')
//   out    = agg * sigmoid(g2w @ hidden + g2b)
//
// Round-5 profile: fma pipe at its 55us floor, issue 51.6%, occ 24.6% ->
// latency-bound at 4 warps/SMSP. This round: sv moves to smem (frees 32 regs)
// and MW moves to const, so __launch_bounds__(256,3) fits 85 regs ->
// 24 warps/SM (+50% latency hiding).
__global__ __launch_bounds__(256, 3) void fused_graphaug_kernel(
    const float* __restrict__ x,
    float* __restrict__ out)
{
    // Per-thread s values, spilled deliberately to smem: [c][t] float2 pairs,
    // lane-stride 8 B -> conflict-free LDS.64. Same-thread RAW, no barrier.
    __shared__ __align__(16) float sSV[C16 * 256 * 2];

    const int t = threadIdx.x;

    // ---- Pixel-pair indexing ----
    const int tidg = blockIdx.x * 256 + t;
    const int p0   = tidg * 2;
    const int w0   = p0 & (W512 - 1);            // even column
    const int h    = (p0 >> 9) & (W512 - 1);
    const int b    = p0 >> 18;

    const float* xb    = x + (size_t)b * C16 * HW;
    const int    center = h * W512 + w0;

    {
        constexpr int DY[8] = {-4, -4, -4, -3, -2, 2, 3, 4};
        constexpr int DX[8] = {-4, -1,  2,  4, -3, 3, -2, 4};
        int roff[8], cb[8];
        #pragma unroll
        for (int i = 0; i < 8; i++) {
            roff[i] = ((h - DY[i]) & (W512 - 1)) * W512;
            cb[i]   = (w0 - DX[i]) & (W512 - 1);
        }

        // ---- s = mean of 8 rolls per channel -> smem ----
        #pragma unroll
        for (int c = 0; c < C16; c++) {
            const float* xp = xb + c * HW;
            float a0 = 0.f, a1 = 0.f;
            #pragma unroll
            for (int i = 0; i < 8; i++) {
                if ((DX[i] & 1) == 0) {
                    float2 v = *reinterpret_cast<const float2*>(xp + roff[i] + cb[i]);
                    a0 += v.x; a1 += v.y;
                } else {
                    a0 += __ldg(xp + roff[i] + cb[i]);
                    a1 += __ldg(xp + roff[i] + ((cb[i] + 1) & (W512 - 1)));
                }
            }
            *reinterpret_cast<float2*>(&sSV[(c * 256 + t) * 2]) =
                make_float2(a0 * 0.125f, a1 * 0.125f);
        }
    }

    // ---- gate accumulators: gacc[gp][px] packs outputs (2gp, 2gp+1) ----
    float2 gacc[8][2];
    #pragma unroll
    for (int gp = 0; gp < 8; gp++) {
        float2 gb = ldc2(OFF_GB + 2 * gp);
        gacc[gp][0] = gb; gacc[gp][1] = gb;
    }

    // ---- hidden in 4 chunks of 8 units ----
    #pragma unroll
    for (int jt = 0; jt < 4; jt++) {
        const int j0 = jt * 8;
        float2 hreg[4][2];
        #pragma unroll
        for (int jl = 0; jl < 4; jl++) {
            float2 bv = ldc2(OFF_B1 + j0 + 2 * jl);
            hreg[jl][0] = bv; hreg[jl][1] = bv;
        }
        // W1 @ x (constant port; x L1/L2-resident reload)
        #pragma unroll
        for (int c = 0; c < C16; c++) {
            float2 xc = *reinterpret_cast<const float2*>(xb + c * HW + center);
            float2 xd0 = dup2(xc.x), xd1 = dup2(xc.y);
            float4 wa = ldc4(OFF_W1 + c * GH32 + j0);
            float4 wb = ldc4(OFF_W1 + c * GH32 + j0 + 4);
            hreg[0][0] = ffma2(make_float2(wa.x, wa.y), xd0, hreg[0][0]);
            hreg[0][1] = ffma2(make_float2(wa.x, wa.y), xd1, hreg[0][1]);
            hreg[1][0] = ffma2(make_float2(wa.z, wa.w), xd0, hreg[1][0]);
            hreg[1][1] = ffma2(make_float2(wa.z, wa.w), xd1, hreg[1][1]);
            hreg[2][0] = ffma2(make_float2(wb.x, wb.y), xd0, hreg[2][0]);
            hreg[2][1] = ffma2(make_float2(wb.x, wb.y), xd1, hreg[2][1]);
            hreg[3][0] = ffma2(make_float2(wb.z, wb.w), xd0, hreg[3][0]);
            hreg[3][1] = ffma2(make_float2(wb.z, wb.w), xd1, hreg[3][1]);
        }
        // W2 @ s (s streamed from smem)
        #pragma unroll
        for (int c = 0; c < C16; c++) {
            float2 sc = *reinterpret_cast<const float2*>(&sSV[(c * 256 + t) * 2]);
            float2 sd0 = dup2(sc.x), sd1 = dup2(sc.y);
            float4 wa = ldc4(OFF_W2 + c * GH32 + j0);
            float4 wb = ldc4(OFF_W2 + c * GH32 + j0 + 4);
            hreg[0][0] = ffma2(make_float2(wa.x, wa.y), sd0, hreg[0][0]);
            hreg[0][1] = ffma2(make_float2(wa.x, wa.y), sd1, hreg[0][1]);
            hreg[1][0] = ffma2(make_float2(wa.z, wa.w), sd0, hreg[1][0]);
            hreg[1][1] = ffma2(make_float2(wa.z, wa.w), sd1, hreg[1][1]);
            hreg[2][0] = ffma2(make_float2(wb.x, wb.y), sd0, hreg[2][0]);
            hreg[2][1] = ffma2(make_float2(wb.x, wb.y), sd1, hreg[2][1]);
            hreg[3][0] = ffma2(make_float2(wb.z, wb.w), sd0, hreg[3][0]);
            hreg[3][1] = ffma2(make_float2(wb.z, wb.w), sd1, hreg[3][1]);
        }
        // relu
        #pragma unroll
        for (int jl = 0; jl < 4; jl++) {
            hreg[jl][0].x = fmaxf(hreg[jl][0].x, 0.f);
            hreg[jl][0].y = fmaxf(hreg[jl][0].y, 0.f);
            hreg[jl][1].x = fmaxf(hreg[jl][1].x, 0.f);
            hreg[jl][1].y = fmaxf(hreg[jl][1].y, 0.f);
        }
        // gate accumulation (constant port)
        #pragma unroll
        for (int jl = 0; jl < 4; jl++) {
            const int jg = j0 + 2 * jl;
            float2 ha0 = dup2(hreg[jl][0].x), hb0 = dup2(hreg[jl][0].y);
            float2 ha1 = dup2(hreg[jl][1].x), hb1 = dup2(hreg[jl][1].y);
            #pragma unroll
            for (int gp = 0; gp < 8; gp++) {
                float4 wq = ldc4(OFF_G2 + gp * 64 + jg * 2);
                gacc[gp][0] = ffma2(make_float2(wq.x, wq.y), ha0, gacc[gp][0]);
                gacc[gp][0] = ffma2(make_float2(wq.z, wq.w), hb0, gacc[gp][0]);
                gacc[gp][1] = ffma2(make_float2(wq.x, wq.y), ha1, gacc[gp][1]);
                gacc[gp][1] = ffma2(make_float2(wq.z, wq.w), hb1, gacc[gp][1]);
            }
        }
    }

    // ---- agg = mw @ s + mb, fused with epilogue per d-pair (keeps regs low):
    //      out = agg * sigmoid(gacc)
    float* ob = out + (size_t)b * C16 * HW + center;
    #pragma unroll
    for (int dp = 0; dp < 8; dp++) {
        float2 mv = ldc2(OFF_MB + 2 * dp);
        float2 ag0 = mv, ag1 = mv;           // ag0: (d0,d1)@px0, ag1: (d0,d1)@px1
        #pragma unroll
        for (int c = 0; c < C16; c += 2) {
            float2 sa = *reinterpret_cast<const float2*>(&sSV[(c * 256 + t) * 2]);
            float2 sb = *reinterpret_cast<const float2*>(&sSV[((c + 1) * 256 + t) * 2]);
            float4 w0 = ldc4(OFF_MW + c * C16 + dp * 2);        // uses only .x,.y
            float4 w1 = ldc4(OFF_MW + (c + 1) * C16 + dp * 2);
            float2 wA = make_float2(w0.x, w0.y);
            float2 wB = make_float2(w1.x, w1.y);
            ag0 = ffma2(wA, dup2(sa.x), ag0);
            ag1 = ffma2(wA, dup2(sa.y), ag1);
            ag0 = ffma2(wB, dup2(sb.x), ag0);
            ag1 = ffma2(wB, dup2(sb.y), ag1);
        }
        const int d0 = 2 * dp;
        float g00 = 1.f / (1.f + __expf(-gacc[dp][0].x));
        float g01 = 1.f / (1.f + __expf(-gacc[dp][1].x));
        float g10 = 1.f / (1.f + __expf(-gacc[dp][0].y));
        float g11 = 1.f / (1.f + __expf(-gacc[dp][1].y));
        *reinterpret_cast<float2*>(ob + (size_t)d0 * HW) =
            make_float2(ag0.x * g00, ag1.x * g01);
        *reinterpret_cast<float2*>(ob + (size_t)(d0 + 1) * HW) =
            make_float2(ag0.y * g10, ag1.y * g11);
    }
}

extern "C" void kernel_launch(void* const* d_in, const int* in_sizes, int n_in,
                              void* d_out, int out_size) {
    // metadata order: x, qw, qb, kw, kb, mw, mb, scaling, g1w, g1b, g2w, g2b
    const float* x   = (const float*)d_in[0];
    const float* mw  = (const float*)d_in[5];
    const float* mb  = (const float*)d_in[6];
    const float* g1w = (const float*)d_in[8];
    const float* g1b = (const float*)d_in[9];
    const float* g2w = (const float*)d_in[10];
    const float* g2b = (const float*)d_in[11];
    float* out = (float*)d_out;

    prep_weights<<<1, 256>>>(mw, mb, g1w, g1b, g2w, g2b);

    void* wsrc = nullptr;
    cudaGetSymbolAddress(&wsrc, g_wbuf);
    cudaMemcpyToSymbolAsync(cwts, wsrc, NWC * sizeof(float), 0,
                            cudaMemcpyDeviceToDevice, 0);

    // 1,048,576 px -> 524,288 horizontal pairs -> 2048 blocks x 256 threads
    fused_graphaug_kernel<<<2048, 256>>>(x, out);
}

// round 7
// speedup vs baseline: 1.9257x; 1.9257x over previous
#include <cuda_runtime.h>

#define C16  16
#define GH32 32
#define W512 512
#define HW   (512 * 512)

// Constant bank: W1/W2 + biases only. G2/MW go to a tiny smem block so the
// weight traffic is split across const-port AND L1 (R5 bound on const+latency).
#define OFF_W1 0        // [c][j]  16*32
#define OFF_W2 512      // [c][j]  16*32  (= g1w[:,16:] @ mw, folded)
#define OFF_B1 1024     // 32            (= g1b + g1w[:,16:] @ mb)
#define OFF_GB 1056     // 16            (g2b)
#define OFF_MB 1072     // 16            (mb)
#define NWC    1088

__constant__ __align__(16) float cwts[NWC];
__device__   __align__(16) float g_wbuf[NWC];

// Packed f32x2 ops (Blackwell sm_103a).
__device__ __forceinline__ float2 ffma2(float2 a, float2 b, float2 c) {
    float2 d;
    asm("fma.rn.f32x2 %0, %1, %2, %3;"
        : "=l"(reinterpret_cast<unsigned long long&>(d))
        : "l"(reinterpret_cast<unsigned long long&>(a)),
          "l"(reinterpret_cast<unsigned long long&>(b)),
          "l"(reinterpret_cast<unsigned long long&>(c)));
    return d;
}
__device__ __forceinline__ float2 fadd2(float2 a, float2 b) {
    float2 d;
    asm("add.rn.f32x2 %0, %1, %2;"
        : "=l"(reinterpret_cast<unsigned long long&>(d))
        : "l"(reinterpret_cast<unsigned long long&>(a)),
          "l"(reinterpret_cast<unsigned long long&>(b)));
    return d;
}
__device__ __forceinline__ float2 dup2(float v) { return make_float2(v, v); }
__device__ __forceinline__ float4 ldc4(int idx) {
    return *reinterpret_cast<const float4*>(&cwts[idx]);
}
__device__ __forceinline__ float2 ldc2(int idx) {
    return *reinterpret_cast<const float2*>(&cwts[idx]);
}

// ---- prep: fold W2 / b1' into constant staging buffer ----
__global__ void prep_weights(const float* __restrict__ mw,  const float* __restrict__ mb,
                             const float* __restrict__ g1w, const float* __restrict__ g1b,
                             const float* __restrict__ g2b)
{
    const int t = threadIdx.x;
    for (int i = t; i < C16 * GH32; i += 256) {
        int c = i >> 5, j = i & 31;
        g_wbuf[OFF_W1 + i] = g1w[j * (2 * C16) + c];
        float acc = 0.f;
        #pragma unroll
        for (int k = 0; k < C16; k++)
            acc += g1w[j * (2 * C16) + C16 + k] * mw[k * C16 + c];
        g_wbuf[OFF_W2 + i] = acc;
    }
    if (t < GH32) {
        float acc = g1b[t];
        #pragma unroll
        for (int k = 0; k < C16; k++)
            acc += g1w[t * (2 * C16) + C16 + k] * mb[k];
        g_wbuf[OFF_B1 + t] = acc;
    }
    if (t >= 32 && t < 32 + C16) g_wbuf[OFF_MB + t - 32] = mb[t - 32];
    if (t >= 64 && t < 64 + C16) g_wbuf[OFF_GB + t - 64] = g2b[t - 64];
}

// Identity: softmax over 8 identical affinities = 1/8 each, so
//   s      = mean of 8 rolls of x
//   agg    = mw @ s + mb
//   hidden = relu(W1 @ x + W2 @ s + b1')
//   out    = agg * sigmoid(g2w @ hidden + g2b)
//
// R5 shape (2 px/thread, sv in regs, 2 blocks/SM) with weight streams split:
// W1/W2 -> const port, G2/MW -> 3 KB smem (L1), x gather -> LDG. Three pipes
// each below the 55us fma floor interleave stalls better at 4 warps/SMSP.
__global__ __launch_bounds__(256, 2) void fused_graphaug_kernel(
    const float* __restrict__ x,
    const float* __restrict__ mw,
    const float* __restrict__ g2w,
    float* __restrict__ out)
{
    __shared__ __align__(16) float sG2[8 * GH32 * 2];  // [gp][j][e] = g2w[2gp+e][j]
    __shared__ __align__(16) float sMW[C16 * C16];     // [c][d]     = mw[d][c]

    const int t = threadIdx.x;
    for (int i = t; i < 8 * GH32 * 2; i += 256) {
        int gp = i >> 6, r = i & 63, j = r >> 1, e = r & 1;
        sG2[i] = g2w[(2 * gp + e) * GH32 + j];
    }
    if (t < 256) {
        int c = t >> 4, d = t & 15;
        sMW[t] = mw[d * C16 + c];
    }
    __syncthreads();

    // ---- Pixel-pair indexing ----
    const int tidg = blockIdx.x * 256 + t;
    const int p0   = tidg * 2;
    const int w0   = p0 & (W512 - 1);            // even column
    const int h    = (p0 >> 9) & (W512 - 1);
    const int b    = p0 >> 18;

    const float* xb    = x + (size_t)b * C16 * HW;
    const int    center = h * W512 + w0;

    // ---- s = mean of 8 rolls per channel (packed f32x2 adds) ----
    float2 sv[C16];
    {
        constexpr int DY[8] = {-4, -4, -4, -3, -2, 2, 3, 4};
        constexpr int DX[8] = {-4, -1,  2,  4, -3, 3, -2, 4};
        int roff[8], cb[8];
        #pragma unroll
        for (int i = 0; i < 8; i++) {
            roff[i] = ((h - DY[i]) & (W512 - 1)) * W512;
            cb[i]   = (w0 - DX[i]) & (W512 - 1);
        }
        #pragma unroll
        for (int c = 0; c < C16; c++) {
            const float* xp = xb + c * HW;
            float2 acc = make_float2(0.f, 0.f);
            #pragma unroll
            for (int i = 0; i < 8; i++) {
                float2 v;
                if ((DX[i] & 1) == 0) {
                    // even dx: cb even <= 510 -> aligned contiguous float2
                    v = *reinterpret_cast<const float2*>(xp + roff[i] + cb[i]);
                } else {
                    v.x = __ldg(xp + roff[i] + cb[i]);
                    v.y = __ldg(xp + roff[i] + ((cb[i] + 1) & (W512 - 1)));
                }
                acc = fadd2(acc, v);
            }
            sv[c] = make_float2(acc.x * 0.125f, acc.y * 0.125f);
        }
    }

    // ---- gate accumulators: gacc[gp][px] packs outputs (2gp, 2gp+1) ----
    float2 gacc[8][2];
    #pragma unroll
    for (int gp = 0; gp < 8; gp++) {
        float2 gb = ldc2(OFF_GB + 2 * gp);
        gacc[gp][0] = gb; gacc[gp][1] = gb;
    }

    // ---- hidden in 4 chunks of 8 units ----
    #pragma unroll
    for (int jt = 0; jt < 4; jt++) {
        const int j0 = jt * 8;
        float2 hreg[4][2];
        #pragma unroll
        for (int jl = 0; jl < 4; jl++) {
            float2 bv = ldc2(OFF_B1 + j0 + 2 * jl);
            hreg[jl][0] = bv; hreg[jl][1] = bv;
        }
        // W1 @ x (const port; x center L1-resident reload)
        #pragma unroll
        for (int c = 0; c < C16; c++) {
            float2 xc = *reinterpret_cast<const float2*>(xb + c * HW + center);
            float2 xd0 = dup2(xc.x), xd1 = dup2(xc.y);
            float4 wa = ldc4(OFF_W1 + c * GH32 + j0);
            float4 wb = ldc4(OFF_W1 + c * GH32 + j0 + 4);
            hreg[0][0] = ffma2(make_float2(wa.x, wa.y), xd0, hreg[0][0]);
            hreg[0][1] = ffma2(make_float2(wa.x, wa.y), xd1, hreg[0][1]);
            hreg[1][0] = ffma2(make_float2(wa.z, wa.w), xd0, hreg[1][0]);
            hreg[1][1] = ffma2(make_float2(wa.z, wa.w), xd1, hreg[1][1]);
            hreg[2][0] = ffma2(make_float2(wb.x, wb.y), xd0, hreg[2][0]);
            hreg[2][1] = ffma2(make_float2(wb.x, wb.y), xd1, hreg[2][1]);
            hreg[3][0] = ffma2(make_float2(wb.z, wb.w), xd0, hreg[3][0]);
            hreg[3][1] = ffma2(make_float2(wb.z, wb.w), xd1, hreg[3][1]);
        }
        // W2 @ s (const port; s in registers)
        #pragma unroll
        for (int c = 0; c < C16; c++) {
            float2 sd0 = dup2(sv[c].x), sd1 = dup2(sv[c].y);
            float4 wa = ldc4(OFF_W2 + c * GH32 + j0);
            float4 wb = ldc4(OFF_W2 + c * GH32 + j0 + 4);
            hreg[0][0] = ffma2(make_float2(wa.x, wa.y), sd0, hreg[0][0]);
            hreg[0][1] = ffma2(make_float2(wa.x, wa.y), sd1, hreg[0][1]);
            hreg[1][0] = ffma2(make_float2(wa.z, wa.w), sd0, hreg[1][0]);
            hreg[1][1] = ffma2(make_float2(wa.z, wa.w), sd1, hreg[1][1]);
            hreg[2][0] = ffma2(make_float2(wb.x, wb.y), sd0, hreg[2][0]);
            hreg[2][1] = ffma2(make_float2(wb.x, wb.y), sd1, hreg[2][1]);
            hreg[3][0] = ffma2(make_float2(wb.z, wb.w), sd0, hreg[3][0]);
            hreg[3][1] = ffma2(make_float2(wb.z, wb.w), sd1, hreg[3][1]);
        }
        // relu
        #pragma unroll
        for (int jl = 0; jl < 4; jl++) {
            hreg[jl][0].x = fmaxf(hreg[jl][0].x, 0.f);
            hreg[jl][0].y = fmaxf(hreg[jl][0].y, 0.f);
            hreg[jl][1].x = fmaxf(hreg[jl][1].x, 0.f);
            hreg[jl][1].y = fmaxf(hreg[jl][1].y, 0.f);
        }
        // gate accumulation (G2 from smem -> L1 pipe, off the const port)
        #pragma unroll
        for (int jl = 0; jl < 4; jl++) {
            const int jg = j0 + 2 * jl;
            float2 ha0 = dup2(hreg[jl][0].x), hb0 = dup2(hreg[jl][0].y);
            float2 ha1 = dup2(hreg[jl][1].x), hb1 = dup2(hreg[jl][1].y);
            #pragma unroll
            for (int gp = 0; gp < 8; gp++) {
                float4 wq = *reinterpret_cast<const float4*>(&sG2[gp * 64 + jg * 2]);
                gacc[gp][0] = ffma2(make_float2(wq.x, wq.y), ha0, gacc[gp][0]);
                gacc[gp][0] = ffma2(make_float2(wq.z, wq.w), hb0, gacc[gp][0]);
                gacc[gp][1] = ffma2(make_float2(wq.x, wq.y), ha1, gacc[gp][1]);
                gacc[gp][1] = ffma2(make_float2(wq.z, wq.w), hb1, gacc[gp][1]);
            }
        }
    }

    // ---- agg = mw @ s + mb (MW from smem), fused epilogue ----
    float* ob = out + (size_t)b * C16 * HW + center;
    #pragma unroll
    for (int dp = 0; dp < 8; dp += 2) {
        float2 mv0 = ldc2(OFF_MB + 2 * dp);
        float2 mv1 = ldc2(OFF_MB + 2 * dp + 2);
        float2 a00 = mv0, a01 = mv0;     // pair (2dp,2dp+1) @ px0 / px1
        float2 a10 = mv1, a11 = mv1;     // pair (2dp+2,2dp+3) @ px0 / px1
        #pragma unroll
        for (int c = 0; c < C16; c++) {
            float2 sd0 = dup2(sv[c].x), sd1 = dup2(sv[c].y);
            float4 wq = *reinterpret_cast<const float4*>(&sMW[c * C16 + dp * 2]);
            a00 = ffma2(make_float2(wq.x, wq.y), sd0, a00);
            a01 = ffma2(make_float2(wq.x, wq.y), sd1, a01);
            a10 = ffma2(make_float2(wq.z, wq.w), sd0, a10);
            a11 = ffma2(make_float2(wq.z, wq.w), sd1, a11);
        }
        #pragma unroll
        for (int e = 0; e < 2; e++) {
            float2 v0 = e ? a10 : a00;           // px0: (d, d+1)
            float2 v1 = e ? a11 : a01;           // px1: (d, d+1)
            const int d0 = 2 * (dp + e);
            float g00 = 1.f / (1.f + __expf(-gacc[dp + e][0].x));
            float g01 = 1.f / (1.f + __expf(-gacc[dp + e][1].x));
            float g10 = 1.f / (1.f + __expf(-gacc[dp + e][0].y));
            float g11 = 1.f / (1.f + __expf(-gacc[dp + e][1].y));
            *reinterpret_cast<float2*>(ob + (size_t)d0 * HW) =
                make_float2(v0.x * g00, v1.x * g01);
            *reinterpret_cast<float2*>(ob + (size_t)(d0 + 1) * HW) =
                make_float2(v0.y * g10, v1.y * g11);
        }
    }
}

extern "C" void kernel_launch(void* const* d_in, const int* in_sizes, int n_in,
                              void* d_out, int out_size) {
    // metadata order: x, qw, qb, kw, kb, mw, mb, scaling, g1w, g1b, g2w, g2b
    const float* x   = (const float*)d_in[0];
    const float* mw  = (const float*)d_in[5];
    const float* mb  = (const float*)d_in[6];
    const float* g1w = (const float*)d_in[8];
    const float* g1b = (const float*)d_in[9];
    const float* g2w = (const float*)d_in[10];
    const float* g2b = (const float*)d_in[11];
    float* out = (float*)d_out;

    prep_weights<<<1, 256>>>(mw, mb, g1w, g1b, g2b);

    void* wsrc = nullptr;
    cudaGetSymbolAddress(&wsrc, g_wbuf);
    cudaMemcpyToSymbolAsync(cwts, wsrc, NWC * sizeof(float), 0,
                            cudaMemcpyDeviceToDevice, 0);

    // 1,048,576 px -> 524,288 horizontal pairs -> 2048 blocks x 256 threads
    fused_graphaug_kernel<<<2048, 256>>>(x, mw, g2w, out);
}

// round 8
// speedup vs baseline: 2.1016x; 1.0913x over previous
#include <cuda_runtime.h>

#define C16  16
#define GH32 32
#define W512 512
#define HW   (512 * 512)

// Constant bank: W1/W2/G2 + biases (the round-5 winning split).
// MW stays in a 1 KB smem block so the const port stays below the fma floor.
#define OFF_W1 0        // [c][j]      16*32
#define OFF_W2 512      // [c][j]      16*32  (= g1w[:,16:] @ mw, folded)
#define OFF_G2 1024     // [gp][j][e]  8*32*2 (= g2w[2gp+e][j])
#define OFF_B1 1536     // 32            (= g1b + g1w[:,16:] @ mb)
#define OFF_GB 1568     // 16            (g2b)
#define OFF_MB 1584     // 16            (mb)
#define NWC    1600

__constant__ __align__(16) float cwts[NWC];
__device__   __align__(16) float g_wbuf[NWC];

// Packed f32x2 ops (Blackwell sm_103a).
__device__ __forceinline__ float2 ffma2(float2 a, float2 b, float2 c) {
    float2 d;
    asm("fma.rn.f32x2 %0, %1, %2, %3;"
        : "=l"(reinterpret_cast<unsigned long long&>(d))
        : "l"(reinterpret_cast<unsigned long long&>(a)),
          "l"(reinterpret_cast<unsigned long long&>(b)),
          "l"(reinterpret_cast<unsigned long long&>(c)));
    return d;
}
__device__ __forceinline__ float2 fadd2(float2 a, float2 b) {
    float2 d;
    asm("add.rn.f32x2 %0, %1, %2;"
        : "=l"(reinterpret_cast<unsigned long long&>(d))
        : "l"(reinterpret_cast<unsigned long long&>(a)),
          "l"(reinterpret_cast<unsigned long long&>(b)));
    return d;
}
__device__ __forceinline__ float2 dup2(float v) { return make_float2(v, v); }
__device__ __forceinline__ float4 ldc4(int idx) {
    return *reinterpret_cast<const float4*>(&cwts[idx]);
}
__device__ __forceinline__ float2 ldc2(int idx) {
    return *reinterpret_cast<const float2*>(&cwts[idx]);
}

// ---- prep: fold weights into constant staging buffer ----
__global__ void prep_weights(const float* __restrict__ mw,  const float* __restrict__ mb,
                             const float* __restrict__ g1w, const float* __restrict__ g1b,
                             const float* __restrict__ g2w, const float* __restrict__ g2b)
{
    const int t = threadIdx.x;
    for (int i = t; i < C16 * GH32; i += 256) {
        int c = i >> 5, j = i & 31;
        g_wbuf[OFF_W1 + i] = g1w[j * (2 * C16) + c];
        float acc = 0.f;
        #pragma unroll
        for (int k = 0; k < C16; k++)
            acc += g1w[j * (2 * C16) + C16 + k] * mw[k * C16 + c];
        g_wbuf[OFF_W2 + i] = acc;
    }
    for (int i = t; i < 8 * GH32 * 2; i += 256) {
        int gp = i >> 6, r = i & 63, j = r >> 1, e = r & 1;
        g_wbuf[OFF_G2 + i] = g2w[(2 * gp + e) * GH32 + j];
    }
    if (t < GH32) {
        float acc = g1b[t];
        #pragma unroll
        for (int k = 0; k < C16; k++)
            acc += g1w[t * (2 * C16) + C16 + k] * mb[k];
        g_wbuf[OFF_B1 + t] = acc;
    }
    if (t >= 32 && t < 32 + C16) g_wbuf[OFF_MB + t - 32] = mb[t - 32];
    if (t >= 64 && t < 64 + C16) g_wbuf[OFF_GB + t - 64] = g2b[t - 64];
}

// Identity: softmax over 8 identical affinities = 1/8 each, so
//   s      = mean of 8 rolls of x
//   agg    = mw @ s + mb
//   hidden = relu(W1 @ x + W2 @ s + b1')
//   out    = agg * sigmoid(g2w @ hidden + g2b)
//
// Round-5 winning shape (2 px/thread, sv in regs, W1/W2/G2 const + MW smem,
// 2 blocks/SM) with issue-slot cuts: f32x2 gather adds, and the hidden loop
// runs in 2 chunks of 16 units (halves center-x reloads + loop overhead).
__global__ __launch_bounds__(256, 2) void fused_graphaug_kernel(
    const float* __restrict__ x,
    const float* __restrict__ mw,
    float* __restrict__ out)
{
    __shared__ __align__(16) float sMW[C16 * C16];   // [c][d] = mw[d][c]
    const int t = threadIdx.x;
    if (t < 256) {
        int c = t >> 4, d = t & 15;
        sMW[t] = mw[d * C16 + c];
    }
    __syncthreads();

    // ---- Pixel-pair indexing ----
    const int tidg = blockIdx.x * 256 + t;
    const int p0   = tidg * 2;
    const int w0   = p0 & (W512 - 1);            // even column
    const int h    = (p0 >> 9) & (W512 - 1);
    const int b    = p0 >> 18;

    const float* xb    = x + (size_t)b * C16 * HW;
    const int    center = h * W512 + w0;

    // ---- s = mean of 8 rolls per channel (packed adds) ----
    float2 sv[C16];
    {
        constexpr int DY[8] = {-4, -4, -4, -3, -2, 2, 3, 4};
        constexpr int DX[8] = {-4, -1,  2,  4, -3, 3, -2, 4};
        int roff[8], cb[8];
        #pragma unroll
        for (int i = 0; i < 8; i++) {
            roff[i] = ((h - DY[i]) & (W512 - 1)) * W512;
            cb[i]   = (w0 - DX[i]) & (W512 - 1);
        }
        #pragma unroll
        for (int c = 0; c < C16; c++) {
            const float* xp = xb + c * HW;
            float2 acc = make_float2(0.f, 0.f);
            #pragma unroll
            for (int i = 0; i < 8; i++) {
                float2 v;
                if ((DX[i] & 1) == 0) {
                    // even dx: cb even <= 510 -> aligned contiguous float2
                    v = *reinterpret_cast<const float2*>(xp + roff[i] + cb[i]);
                } else {
                    v.x = __ldg(xp + roff[i] + cb[i]);
                    v.y = __ldg(xp + roff[i] + ((cb[i] + 1) & (W512 - 1)));
                }
                acc = fadd2(acc, v);
            }
            sv[c] = make_float2(acc.x * 0.125f, acc.y * 0.125f);
        }
    }

    // ---- gate accumulators: gacc[gp][px] packs outputs (2gp, 2gp+1) ----
    float2 gacc[8][2];
    #pragma unroll
    for (int gp = 0; gp < 8; gp++) {
        float2 gb = ldc2(OFF_GB + 2 * gp);
        gacc[gp][0] = gb; gacc[gp][1] = gb;
    }

    // ---- hidden in 2 chunks of 16 units (8 j-pairs each) ----
    #pragma unroll
    for (int jt = 0; jt < 2; jt++) {
        const int j0 = jt * 16;
        float2 hreg[8][2];                       // pairs (j0+2l, j0+2l+1) x 2 px
        #pragma unroll
        for (int jl = 0; jl < 8; jl++) {
            float2 bv = ldc2(OFF_B1 + j0 + 2 * jl);
            hreg[jl][0] = bv; hreg[jl][1] = bv;
        }
        // W1 @ x (const port; x center loaded once per chunk, L1-resident)
        #pragma unroll
        for (int c = 0; c < C16; c++) {
            float2 xc = *reinterpret_cast<const float2*>(xb + c * HW + center);
            float2 xd0 = dup2(xc.x), xd1 = dup2(xc.y);
            #pragma unroll
            for (int q = 0; q < 4; q++) {        // 4 ldc4 cover 16 units
                float4 wq = ldc4(OFF_W1 + c * GH32 + j0 + 4 * q);
                hreg[2*q][0]   = ffma2(make_float2(wq.x, wq.y), xd0, hreg[2*q][0]);
                hreg[2*q][1]   = ffma2(make_float2(wq.x, wq.y), xd1, hreg[2*q][1]);
                hreg[2*q+1][0] = ffma2(make_float2(wq.z, wq.w), xd0, hreg[2*q+1][0]);
                hreg[2*q+1][1] = ffma2(make_float2(wq.z, wq.w), xd1, hreg[2*q+1][1]);
            }
        }
        // W2 @ s (const port; s in registers)
        #pragma unroll
        for (int c = 0; c < C16; c++) {
            float2 sd0 = dup2(sv[c].x), sd1 = dup2(sv[c].y);
            #pragma unroll
            for (int q = 0; q < 4; q++) {
                float4 wq = ldc4(OFF_W2 + c * GH32 + j0 + 4 * q);
                hreg[2*q][0]   = ffma2(make_float2(wq.x, wq.y), sd0, hreg[2*q][0]);
                hreg[2*q][1]   = ffma2(make_float2(wq.x, wq.y), sd1, hreg[2*q][1]);
                hreg[2*q+1][0] = ffma2(make_float2(wq.z, wq.w), sd0, hreg[2*q+1][0]);
                hreg[2*q+1][1] = ffma2(make_float2(wq.z, wq.w), sd1, hreg[2*q+1][1]);
            }
        }
        // relu
        #pragma unroll
        for (int jl = 0; jl < 8; jl++) {
            hreg[jl][0].x = fmaxf(hreg[jl][0].x, 0.f);
            hreg[jl][0].y = fmaxf(hreg[jl][0].y, 0.f);
            hreg[jl][1].x = fmaxf(hreg[jl][1].x, 0.f);
            hreg[jl][1].y = fmaxf(hreg[jl][1].y, 0.f);
        }
        // gate accumulation (const port)
        #pragma unroll
        for (int jl = 0; jl < 8; jl++) {
            const int jg = j0 + 2 * jl;
            float2 ha0 = dup2(hreg[jl][0].x), hb0 = dup2(hreg[jl][0].y);
            float2 ha1 = dup2(hreg[jl][1].x), hb1 = dup2(hreg[jl][1].y);
            #pragma unroll
            for (int gp = 0; gp < 8; gp++) {
                float4 wq = ldc4(OFF_G2 + gp * 64 + jg * 2);
                gacc[gp][0] = ffma2(make_float2(wq.x, wq.y), ha0, gacc[gp][0]);
                gacc[gp][0] = ffma2(make_float2(wq.z, wq.w), hb0, gacc[gp][0]);
                gacc[gp][1] = ffma2(make_float2(wq.x, wq.y), ha1, gacc[gp][1]);
                gacc[gp][1] = ffma2(make_float2(wq.z, wq.w), hb1, gacc[gp][1]);
            }
        }
    }

    // ---- agg = mw @ s + mb (MW from smem), fused epilogue per d-pair ----
    float* ob = out + (size_t)b * C16 * HW + center;
    #pragma unroll
    for (int dp = 0; dp < 8; dp += 2) {
        float2 mv0 = ldc2(OFF_MB + 2 * dp);
        float2 mv1 = ldc2(OFF_MB + 2 * dp + 2);
        float2 a00 = mv0, a01 = mv0;     // pair (2dp,2dp+1)   @ px0 / px1
        float2 a10 = mv1, a11 = mv1;     // pair (2dp+2,2dp+3) @ px0 / px1
        #pragma unroll
        for (int c = 0; c < C16; c++) {
            float2 sd0 = dup2(sv[c].x), sd1 = dup2(sv[c].y);
            float4 wq = *reinterpret_cast<const float4*>(&sMW[c * C16 + dp * 2]);
            a00 = ffma2(make_float2(wq.x, wq.y), sd0, a00);
            a01 = ffma2(make_float2(wq.x, wq.y), sd1, a01);
            a10 = ffma2(make_float2(wq.z, wq.w), sd0, a10);
            a11 = ffma2(make_float2(wq.z, wq.w), sd1, a11);
        }
        #pragma unroll
        for (int e = 0; e < 2; e++) {
            float2 v0 = e ? a10 : a00;           // px0: (d, d+1)
            float2 v1 = e ? a11 : a01;           // px1: (d, d+1)
            const int d0 = 2 * (dp + e);
            float g00 = 1.f / (1.f + __expf(-gacc[dp + e][0].x));
            float g01 = 1.f / (1.f + __expf(-gacc[dp + e][1].x));
            float g10 = 1.f / (1.f + __expf(-gacc[dp + e][0].y));
            float g11 = 1.f / (1.f + __expf(-gacc[dp + e][1].y));
            *reinterpret_cast<float2*>(ob + (size_t)d0 * HW) =
                make_float2(v0.x * g00, v1.x * g01);
            *reinterpret_cast<float2*>(ob + (size_t)(d0 + 1) * HW) =
                make_float2(v0.y * g10, v1.y * g11);
        }
    }
}

extern "C" void kernel_launch(void* const* d_in, const int* in_sizes, int n_in,
                              void* d_out, int out_size) {
    // metadata order: x, qw, qb, kw, kb, mw, mb, scaling, g1w, g1b, g2w, g2b
    const float* x   = (const float*)d_in[0];
    const float* mw  = (const float*)d_in[5];
    const float* mb  = (const float*)d_in[6];
    const float* g1w = (const float*)d_in[8];
    const float* g1b = (const float*)d_in[9];
    const float* g2w = (const float*)d_in[10];
    const float* g2b = (const float*)d_in[11];
    float* out = (float*)d_out;

    prep_weights<<<1, 256>>>(mw, mb, g1w, g1b, g2w, g2b);

    void* wsrc = nullptr;
    cudaGetSymbolAddress(&wsrc, g_wbuf);
    cudaMemcpyToSymbolAsync(cwts, wsrc, NWC * sizeof(float), 0,
                            cudaMemcpyDeviceToDevice, 0);

    // 1,048,576 px -> 524,288 horizontal pairs -> 2048 blocks x 256 threads
    fused_graphaug_kernel<<<2048, 256>>>(x, mw, out);
}